// round 14
// baseline (speedup 1.0000x reference)
#include <cuda_runtime.h>
#include <cuda_fp16.h>
#include <stdint.h>

#define CCH 128
#define THREADS 256
#define GRIDP 296            // 2 CTAs/SM x 148 SMs, all co-resident

// ---- device scratch ----
__device__ float    g_bias[32 * CCH];
__device__ uint32_t g_Wtm[CCH][128];        // [o][k/2] fp16x2 of Acat=[W0 W1]
__device__ float    g_bufA[262144 * 128];
__device__ float    g_bufB[131072 * 128];
__device__ int      g_barCount;
__device__ volatile unsigned g_barGen;

// ---- SMEM layout (bytes) ----
#define SM_XH   0                    // X hi: 65 rows x 256B = 16640
#define SM_XL   16640                // X lo
#define SM_WH   33280                // W: 128 rows x 512B (fp16 single plane)
#define SM_STAGE 98816               // 16 rows x 136 floats = 8704
#define SM_TOT   107520
#define STAGE_STRIDE 136

__device__ __forceinline__ uint32_t smem_u32(const void* p) {
    uint32_t a;
    asm("{ .reg .u64 t; cvta.to.shared.u64 t, %1; cvt.u32.u64 %0, t; }" : "=r"(a) : "l"(p));
    return a;
}
__device__ __forceinline__ void ldx4(uint32_t& r0, uint32_t& r1, uint32_t& r2, uint32_t& r3,
                                     uint32_t addr) {
    asm volatile("ldmatrix.sync.aligned.m8n8.x4.shared.b16 {%0,%1,%2,%3}, [%4];"
                 : "=r"(r0), "=r"(r1), "=r"(r2), "=r"(r3) : "r"(addr));
}
__device__ __forceinline__ void mma_f16(float* d, const uint32_t* a, const uint32_t* b) {
    asm volatile("mma.sync.aligned.m16n8k16.row.col.f32.f16.f16.f32 "
                 "{%0,%1,%2,%3}, {%4,%5,%6,%7}, {%8,%9}, {%0,%1,%2,%3};"
                 : "+f"(d[0]), "+f"(d[1]), "+f"(d[2]), "+f"(d[3])
                 : "r"(a[0]), "r"(a[1]), "r"(a[2]), "r"(a[3]), "r"(b[0]), "r"(b[1]));
}
#define STS64(addr, x, y) \
    asm volatile("st.shared.v2.u32 [%0], {%1,%2};" :: "r"(addr), "r"(x), "r"(y) : "memory")

// split float4 into fp16 hi plane + fp16 residual plane (x = hi + lo to ~2^-23)
__device__ __forceinline__ void cvt_sts(float4 v, uint32_t dstH, uint32_t dstL) {
    __half h0 = __float2half_rn(v.x), h1 = __float2half_rn(v.y);
    __half h2 = __float2half_rn(v.z), h3 = __float2half_rn(v.w);
    __half l0 = __float2half_rn(v.x - __half2float(h0));
    __half l1 = __float2half_rn(v.y - __half2float(h1));
    __half l2 = __float2half_rn(v.z - __half2float(h2));
    __half l3 = __float2half_rn(v.w - __half2float(h3));
    __half2 hp0 = {h0, h1}, hp1 = {h2, h3}, lp0 = {l0, l1}, lp1 = {l2, l3};
    STS64(dstH, *(uint32_t*)&hp0, *(uint32_t*)&hp1);
    STS64(dstL, *(uint32_t*)&lp0, *(uint32_t*)&lp1);
}

// sense-reversing grid barrier; safe: all GRIDP CTAs co-resident (2 CTA/SM).
__device__ __forceinline__ void grid_barrier() {
    __syncthreads();
    if (threadIdx.x == 0) {
        unsigned gen = g_barGen;
        __threadfence();
        if (atomicAdd(&g_barCount, 1) == (int)gridDim.x - 1) {
            g_barCount = 0;
            __threadfence();
            g_barGen = gen + 1;
        } else {
            while (g_barGen == gen) { }
        }
        __threadfence();
    }
    __syncthreads();
}

// ---------------------------------------------------------------------------
__global__ void precompute_kernel(const float* __restrict__ W,
                                  const float* __restrict__ b,
                                  const float* __restrict__ depth,
                                  int nlev) {
    const int tid = threadIdx.x;
    const int gid = blockIdx.x * blockDim.x + tid;
    const int gsize = gridDim.x * blockDim.x;

    for (int i = gid; i < CCH * 128; i += gsize) {
        int o = (i >> 7) & 127, col = i & 127;
        uint32_t out = 0;
        #pragma unroll
        for (int h = 0; h < 2; ++h) {
            int c = 2 * col + h;
            float w = (c < 128) ? W[(size_t)o * 512 + c * 2]
                                : W[(size_t)o * 512 + (c - 128) * 2 + 1];
            __half hv = __float2half_rn(w);
            uint16_t bits = *(uint16_t*)&hv;
            out |= (uint32_t)bits << (16 * h);
        }
        g_Wtm[o][col] = out;
    }

    const int l = tid & 31;
    const int gw = gid >> 5;
    const int nwarps = gsize >> 5;
    for (int p = gw; p < nlev * CCH; p += nwarps) {
        const int lev = p >> 7, o = p & 127;
        float s = 0.f;
        #pragma unroll
        for (int cc = 0; cc < 4; ++cc) {
            int c = l + cc * 32;
            float ws = W[(size_t)o * 512 + (128 + c) * 2 + 0] +
                       W[(size_t)o * 512 + (128 + c) * 2 + 1];
            s += ws * depth[lev * CCH + c];
        }
        #pragma unroll
        for (int d = 16; d > 0; d >>= 1)
            s += __shfl_xor_sync(0xffffffffu, s, d);
        if (l == 0) g_bias[lev * CCH + o] = b[o] + s;
    }
}

// ---------------------------------------------------------------------------
// Persistent, 2 CTAs/SM. Unpipelined tile loop — occupancy hides latency.
// fp16 split-2: D = (Xh + Xl) * Wh, fp32 accum. 64-pos tiles, 8 warps 2mx4n.
// ---------------------------------------------------------------------------
__global__ __launch_bounds__(THREADS, 2)
void persistent_kernel(const float* __restrict__ Xin, const int* __restrict__ perm,
                       float* bufA, float* bufB, float* outp, int N) {
    extern __shared__ char smem[];
    const uint32_t sb = smem_u32(smem);
    float* stagef = (float*)(smem + SM_STAGE);
    const int tid = threadIdx.x, l = tid & 31, wid = tid >> 5;
    const int wm = (wid >> 2) * 32, wn = (wid & 3) * 32;
    const int bid = blockIdx.x;

    // ---- W -> smem once ----
    for (int i = tid; i < 128 * 64; i += THREADS) {
        int o = i >> 6, u = i & 63;
        uint2 v = ((const uint2*)&g_Wtm[o][0])[u];
        uint32_t byte = (uint32_t)o * 512 + (((uint32_t)u * 8) ^ (uint32_t)((o & 7) << 4));
        STS64(sb + SM_WH + byte, v.x, v.y);
    }

    // ---- fragment address constants ----
    const int arl = ((l >> 3) & 1) * 8 + (l & 7);
    uint32_t aAddr[2][2], aS[2][2];
    #pragma unroll
    for (int mt = 0; mt < 2; ++mt)
        #pragma unroll
        for (int tap = 0; tap < 2; ++tap) {
            int row = wm + mt * 16 + arl + tap;
            aAddr[mt][tap] = (uint32_t)row * 256;
            aS[mt][tap] = (uint32_t)((row & 7) << 4);
        }
    uint32_t bRow[2], bS[2];
    #pragma unroll
    for (int g = 0; g < 2; ++g) {
        int o = wn + g * 16 + ((l >> 4) & 1) * 8 + (l & 7);
        bRow[g] = (uint32_t)o * 512;
        bS[g] = (uint32_t)((o & 7) << 4);
    }
    const uint32_t a_k8b = ((l >> 4) & 1) * 16;
    const uint32_t b_k8b = ((l >> 3) & 1) * 16;
    const uint32_t xswz = ((uint32_t)l * 8) ^ ((uint32_t)wid << 4);

    const float* Xcur = Xin;
    int L = N;

    for (int lvl = 0; L > 1; ++lvl) {
        const int Lout = (L - 1) >> 1;
        float* Yout = (Lout == 1) ? outp : ((lvl & 1) ? bufB : bufA);
        const int* pm = (lvl == 0) ? perm : nullptr;
        const int ntiles = (Lout + 31) >> 5;

        float bx[4], by[4];
        #pragma unroll
        for (int nt = 0; nt < 4; ++nt) {
            float2 bb = *(const float2*)&g_bias[lvl * CCH + wn + nt * 8 + (l & 3) * 2];
            bx[nt] = bb.x; by[nt] = bb.y;
        }

        for (int tile = bid; tile < ntiles; tile += GRIDP) {
            // ---- 1. load X tile (65 rows x 128 ch, fp16 hi/lo split) ----
            const int pbase = tile << 6;
            #pragma unroll
            for (int s9 = 0; s9 < 9; ++s9) {
                if (s9 == 8 && wid != 0) break;
                int row = s9 * 8 + wid;
                int pin = pbase + row; if (pin > L - 1) pin = L - 1;
                size_t srow = pm ? (size_t)pm[pin] : (size_t)pin;
                float4 v = *((const float4*)(Xcur + srow * CCH) + l);
                uint32_t byte = (uint32_t)row * 256 + xswz;
                cvt_sts(v, sb + SM_XH + byte, sb + SM_XL + byte);
            }
            __syncthreads();

            // ---- 2. MMA: 2 fp16 products ----
            float acc[2][4][4];
            #pragma unroll
            for (int mt = 0; mt < 2; ++mt)
                #pragma unroll
                for (int nt = 0; nt < 4; ++nt)
                    #pragma unroll
                    for (int r = 0; r < 4; ++r) acc[mt][nt][r] = 0.f;

            #pragma unroll
            for (int kt = 0; kt < 16; ++kt) {
                const int tap = kt >> 3;
                const uint32_t chA = (uint32_t)(kt & 7) * 32 + a_k8b;
                const uint32_t chB = (uint32_t)kt * 32 + b_k8b;

                uint32_t Bh[4][2];
                ldx4(Bh[0][0], Bh[0][1], Bh[1][0], Bh[1][1], sb + SM_WH + bRow[0] + (chB ^ bS[0]));
                ldx4(Bh[2][0], Bh[2][1], Bh[3][0], Bh[3][1], sb + SM_WH + bRow[1] + (chB ^ bS[1]));

                #pragma unroll
                for (int mt = 0; mt < 2; ++mt) {
                    const uint32_t aoff = aAddr[mt][tap] + (chA ^ aS[mt][tap]);
                    uint32_t Ah[4], Al[4];
                    ldx4(Ah[0], Ah[1], Ah[2], Ah[3], sb + SM_XH + aoff);
                    ldx4(Al[0], Al[1], Al[2], Al[3], sb + SM_XL + aoff);
                    #pragma unroll
                    for (int nt = 0; nt < 4; ++nt) {
                        mma_f16(acc[mt][nt], Ah, Bh[nt]);
                        mma_f16(acc[mt][nt], Al, Bh[nt]);
                    }
                }
            }

            // ---- 3. epilogue: bias + leaky + pool(2) in regs ----
            const int r2 = l >> 2;
            const bool storer = ((r2 & 1) == 0);
            #pragma unroll
            for (int mt = 0; mt < 2; ++mt)
                #pragma unroll
                for (int nt = 0; nt < 4; ++nt) {
                    float* d = acc[mt][nt];
                    float v0 = d[0] + bx[nt], v1 = d[1] + by[nt];
                    float v2 = d[2] + bx[nt], v3 = d[3] + by[nt];
                    v0 = v0 >= 0.f ? v0 : 0.2f * v0;
                    v1 = v1 >= 0.f ? v1 : 0.2f * v1;
                    v2 = v2 >= 0.f ? v2 : 0.2f * v2;
                    v3 = v3 >= 0.f ? v3 : 0.2f * v3;
                    d[0] = fmaxf(v0, __shfl_xor_sync(0xffffffffu, v0, 4));
                    d[1] = fmaxf(v1, __shfl_xor_sync(0xffffffffu, v1, 4));
                    d[2] = fmaxf(v2, __shfl_xor_sync(0xffffffffu, v2, 4));
                    d[3] = fmaxf(v3, __shfl_xor_sync(0xffffffffu, v3, 4));
                }

            // ---- 4. two 16-row stage passes -> coalesced stores ----
            const int jbase = tile << 5;
            #pragma unroll
            for (int h = 0; h < 2; ++h) {
                if (storer) {
                    #pragma unroll
                    for (int mt = 0; mt < 2; ++mt)
                        #pragma unroll
                        for (int nt = 0; nt < 4; ++nt) {
                            float* d = acc[mt][nt];
                            const int o0 = wn + nt * 8 + (l & 3) * 2;
                            const int jl = (wm + mt * 16 + r2) >> 1;   // 0..27
                            if ((jl >> 4) == h)
                                *(float2*)&stagef[(jl - h * 16) * STAGE_STRIDE + o0] =
                                    make_float2(d[0], d[1]);
                            if (((jl + 4) >> 4) == h)
                                *(float2*)&stagef[(jl + 4 - h * 16) * STAGE_STRIDE + o0] =
                                    make_float2(d[2], d[3]);
                        }
                }
                __syncthreads();   // stage pass written (also: all MMA X reads done)
                #pragma unroll
                for (int k = 0; k < 2; ++k) {
                    int idx = tid + k * THREADS;            // 0..511
                    int row = idx >> 5, c4 = idx & 31;
                    int j = jbase + h * 16 + row;
                    if (j < Lout) {
                        float4 v = *(const float4*)&stagef[row * STAGE_STRIDE + c4 * 4];
                        *(float4*)&Yout[(size_t)j * CCH + c4 * 4] = v;
                    }
                }
                __syncthreads();   // stage free (and X safe to overwrite next tile)
            }
        }

        grid_barrier();
        Xcur = Yout;
        L = Lout;
    }
}

// ---------------------------------------------------------------------------
extern "C" void kernel_launch(void* const* d_in, const int* in_sizes, int n_in,
                              void* d_out, int out_size) {
    const float* x     = (const float*)d_in[0];
    const float* depth = (const float*)d_in[1];
    const float* W     = (const float*)d_in[2];
    const float* b     = (const float*)d_in[3];
    const int*   perm  = (const int*)d_in[4];
    float* out = (float*)d_out;

    int N = in_sizes[0] / CCH;
    int nlev = 0;
    { int L = N; while (L > 1) { L = (L - 1) / 2; nlev++; } }

    cudaFuncSetAttribute((const void*)persistent_kernel,
                         cudaFuncAttributeMaxDynamicSharedMemorySize, SM_TOT);

    precompute_kernel<<<GRIDP, 256>>>(W, b, depth, nlev);

    float *bufA, *bufB;
    cudaGetSymbolAddress((void**)&bufA, g_bufA);
    cudaGetSymbolAddress((void**)&bufB, g_bufB);

    persistent_kernel<<<GRIDP, THREADS, SM_TOT>>>(x, perm, bufA, bufB, out, N);
}

// round 15
// speedup vs baseline: 2.0730x; 2.0730x over previous
#include <cuda_runtime.h>
#include <cuda_fp16.h>
#include <stdint.h>

#define CCH 128
#define THREADS 256
#define GRIDP 148            // persistent grid: 1 CTA/SM, all co-resident

// ---- device scratch ----
__device__ float    g_bias[32 * CCH];
__device__ uint32_t g_Wtm[CCH][128];        // [o][k/2] fp16x2 of Acat=[W0 W1]
__device__ float    g_bufA[262144 * 128];
__device__ float    g_bufB[131072 * 128];
__device__ int      g_barCount;
__device__ volatile unsigned g_barGen;

// ---- SMEM layout (bytes) ----
// X double buffer: 65 rows x 256B = 16640 each (single fp16 plane)
#define XBUF(buf) ((buf) * 16640)
#define SM_WH  33280                 // W: 128 rows x 512B (fp16 single plane)
#define SM_STAGE 98816               // 32 rows x 136 floats = 17408 B
#define SM_TOT  116224
#define STAGE_STRIDE 136

__device__ __forceinline__ uint32_t smem_u32(const void* p) {
    uint32_t a;
    asm("{ .reg .u64 t; cvta.to.shared.u64 t, %1; cvt.u32.u64 %0, t; }" : "=r"(a) : "l"(p));
    return a;
}
__device__ __forceinline__ void ldx4(uint32_t& r0, uint32_t& r1, uint32_t& r2, uint32_t& r3,
                                     uint32_t addr) {
    asm volatile("ldmatrix.sync.aligned.m8n8.x4.shared.b16 {%0,%1,%2,%3}, [%4];"
                 : "=r"(r0), "=r"(r1), "=r"(r2), "=r"(r3) : "r"(addr));
}
__device__ __forceinline__ void mma_f16(float* d, const uint32_t* a, const uint32_t* b) {
    asm volatile("mma.sync.aligned.m16n8k16.row.col.f32.f16.f16.f32 "
                 "{%0,%1,%2,%3}, {%4,%5,%6,%7}, {%8,%9}, {%0,%1,%2,%3};"
                 : "+f"(d[0]), "+f"(d[1]), "+f"(d[2]), "+f"(d[3])
                 : "r"(a[0]), "r"(a[1]), "r"(a[2]), "r"(a[3]), "r"(b[0]), "r"(b[1]));
}
#define STS64(addr, x, y) \
    asm volatile("st.shared.v2.u32 [%0], {%1,%2};" :: "r"(addr), "r"(x), "r"(y) : "memory")

// convert float4 -> fp16x4 and store to the single X plane
__device__ __forceinline__ void cvt_sts(float4 v, uint32_t dstH) {
    __half2 hp0 = {__float2half_rn(v.x), __float2half_rn(v.y)};
    __half2 hp1 = {__float2half_rn(v.z), __float2half_rn(v.w)};
    STS64(dstH, *(uint32_t*)&hp0, *(uint32_t*)&hp1);
}

// sense-reversing grid barrier; safe: all GRIDP CTAs co-resident (1 CTA/SM).
__device__ __forceinline__ void grid_barrier() {
    __syncthreads();
    if (threadIdx.x == 0) {
        unsigned gen = g_barGen;
        __threadfence();
        if (atomicAdd(&g_barCount, 1) == (int)gridDim.x - 1) {
            g_barCount = 0;
            __threadfence();
            g_barGen = gen + 1;
        } else {
            while (g_barGen == gen) { }
        }
        __threadfence();
    }
    __syncthreads();
}

// ---------------------------------------------------------------------------
// Parallel precompute: W -> fp16 plane; per-level bias via warp dot products.
// ---------------------------------------------------------------------------
__global__ void precompute_kernel(const float* __restrict__ W,
                                  const float* __restrict__ b,
                                  const float* __restrict__ depth,
                                  int nlev) {
    const int tid = threadIdx.x;
    const int gid = blockIdx.x * blockDim.x + tid;
    const int gsize = gridDim.x * blockDim.x;

    for (int i = gid; i < CCH * 128; i += gsize) {
        int o = (i >> 7) & 127, col = i & 127;
        uint32_t out = 0;
        #pragma unroll
        for (int h = 0; h < 2; ++h) {
            int c = 2 * col + h;
            float w = (c < 128) ? W[(size_t)o * 512 + c * 2]
                                : W[(size_t)o * 512 + (c - 128) * 2 + 1];
            __half hv = __float2half_rn(w);
            uint16_t bits = *(uint16_t*)&hv;
            out |= (uint32_t)bits << (16 * h);
        }
        g_Wtm[o][col] = out;
    }

    const int l = tid & 31;
    const int gw = gid >> 5;
    const int nwarps = gsize >> 5;
    for (int p = gw; p < nlev * CCH; p += nwarps) {
        const int lev = p >> 7, o = p & 127;
        float s = 0.f;
        #pragma unroll
        for (int cc = 0; cc < 4; ++cc) {
            int c = l + cc * 32;
            float ws = W[(size_t)o * 512 + (128 + c) * 2 + 0] +
                       W[(size_t)o * 512 + (128 + c) * 2 + 1];
            s += ws * depth[lev * CCH + c];
        }
        #pragma unroll
        for (int d = 16; d > 0; d >>= 1)
            s += __shfl_xor_sync(0xffffffffu, s, d);
        if (l == 0) g_bias[lev * CCH + o] = b[o] + s;
    }
}

// ---------------------------------------------------------------------------
// Persistent: all levels, one launch; grid barrier between levels.
// Single-product fp16: D = Xh * Wh, fp32 accum. R13 structure otherwise.
// ---------------------------------------------------------------------------
__global__ __launch_bounds__(THREADS)
void persistent_kernel(const float* __restrict__ Xin, const int* __restrict__ perm,
                       float* bufA, float* bufB, float* outp, int N) {
    extern __shared__ char smem[];
    const uint32_t sb = smem_u32(smem);
    float* stagef = (float*)(smem + SM_STAGE);
    const int tid = threadIdx.x, l = tid & 31, wid = tid >> 5;
    const int wm = (wid >> 2) * 32, wn = (wid & 3) * 32;
    const int bid = blockIdx.x;

    // ---- W -> smem once for the whole run ----
    for (int i = tid; i < 128 * 64; i += THREADS) {
        int o = i >> 6, u = i & 63;
        uint2 v = ((const uint2*)&g_Wtm[o][0])[u];
        uint32_t byte = (uint32_t)o * 512 + (((uint32_t)u * 8) ^ (uint32_t)((o & 7) << 4));
        STS64(sb + SM_WH + byte, v.x, v.y);
    }

    // ---- per-lane fragment address constants ----
    const int arl = ((l >> 3) & 1) * 8 + (l & 7);
    uint32_t aAddr[2][2], aS[2][2];
    #pragma unroll
    for (int mt = 0; mt < 2; ++mt)
        #pragma unroll
        for (int tap = 0; tap < 2; ++tap) {
            int row = wm + mt * 16 + arl + tap;
            aAddr[mt][tap] = (uint32_t)row * 256;
            aS[mt][tap] = (uint32_t)((row & 7) << 4);
        }
    uint32_t bRow[2], bS[2];
    #pragma unroll
    for (int g = 0; g < 2; ++g) {
        int o = wn + g * 16 + ((l >> 4) & 1) * 8 + (l & 7);
        bRow[g] = (uint32_t)o * 512;
        bS[g] = (uint32_t)((o & 7) << 4);
    }
    const uint32_t a_k8b = ((l >> 4) & 1) * 16;
    const uint32_t b_k8b = ((l >> 3) & 1) * 16;
    const uint32_t xswz = ((uint32_t)l * 8) ^ ((uint32_t)wid << 4);

    const float* Xcur = Xin;
    int L = N;

    for (int lvl = 0; L > 1; ++lvl) {
        const int Lout = (L - 1) >> 1;
        float* Yout = (Lout == 1) ? outp : ((lvl & 1) ? bufB : bufA);
        const int* pm = (lvl == 0) ? perm : nullptr;
        const int ntiles = (Lout + 31) >> 5;

        float bx[4], by[4];
        #pragma unroll
        for (int nt = 0; nt < 4; ++nt) {
            float2 bb = *(const float2*)&g_bias[lvl * CCH + wn + nt * 8 + (l & 3) * 2];
            bx[nt] = bb.x; by[nt] = bb.y;
        }

        // ---- prologue: load first tile into buf 0 ----
        int cur = 0;
        if (bid < ntiles) {
            const int pbase = bid << 6;
            #pragma unroll
            for (int s9 = 0; s9 < 9; ++s9) {
                if (s9 == 8 && wid != 0) break;
                int row = s9 * 8 + wid;
                int pin = pbase + row; if (pin > L - 1) pin = L - 1;
                size_t srow = pm ? (size_t)pm[pin] : (size_t)pin;
                float4 v = *((const float4*)(Xcur + srow * CCH) + l);
                cvt_sts(v, sb + XBUF(0) + (uint32_t)row * 256 + xswz);
            }
        }
        __syncthreads();

        for (int tile = bid; tile < ntiles; tile += GRIDP) {
            const int nexttile = tile + GRIDP;
            const bool hasnext = nexttile < ntiles;

            // ---- 1. prefetch next tile's X into registers ----
            float4 pr[9];
            if (hasnext) {
                const int pbase = nexttile << 6;
                #pragma unroll
                for (int s9 = 0; s9 < 9; ++s9) {
                    if (s9 == 8 && wid != 0) break;
                    int row = s9 * 8 + wid;
                    int pin = pbase + row; if (pin > L - 1) pin = L - 1;
                    size_t srow = pm ? (size_t)pm[pin] : (size_t)pin;
                    pr[s9] = *((const float4*)(Xcur + srow * CCH) + l);
                }
            }

            // ---- 2. MMA from buf[cur]: single fp16 product ----
            float acc[2][4][4];
            #pragma unroll
            for (int mt = 0; mt < 2; ++mt)
                #pragma unroll
                for (int nt = 0; nt < 4; ++nt)
                    #pragma unroll
                    for (int r = 0; r < 4; ++r) acc[mt][nt][r] = 0.f;

            const uint32_t xbH = sb + XBUF(cur);
            #pragma unroll
            for (int kt = 0; kt < 16; ++kt) {
                const int tap = kt >> 3;
                const uint32_t chA = (uint32_t)(kt & 7) * 32 + a_k8b;
                const uint32_t chB = (uint32_t)kt * 32 + b_k8b;

                uint32_t Bh[4][2];
                ldx4(Bh[0][0], Bh[0][1], Bh[1][0], Bh[1][1], sb + SM_WH + bRow[0] + (chB ^ bS[0]));
                ldx4(Bh[2][0], Bh[2][1], Bh[3][0], Bh[3][1], sb + SM_WH + bRow[1] + (chB ^ bS[1]));

                #pragma unroll
                for (int mt = 0; mt < 2; ++mt) {
                    const uint32_t aoff = aAddr[mt][tap] + (chA ^ aS[mt][tap]);
                    uint32_t Ah[4];
                    ldx4(Ah[0], Ah[1], Ah[2], Ah[3], xbH + aoff);
                    #pragma unroll
                    for (int nt = 0; nt < 4; ++nt)
                        mma_f16(acc[mt][nt], Ah, Bh[nt]);
                }
            }

            // ---- 3. cvt + STS prefetched tile into buf[cur^1] ----
            if (hasnext) {
                const uint32_t dH = sb + XBUF(cur ^ 1);
                #pragma unroll
                for (int s9 = 0; s9 < 9; ++s9) {
                    if (s9 == 8 && wid != 0) break;
                    cvt_sts(pr[s9], dH + (uint32_t)(s9 * 8 + wid) * 256 + xswz);
                }
            }

            // ---- 4. epilogue: bias + leaky + pool(2) -> stage ----
            const int r2 = l >> 2;
            const bool storer = ((r2 & 1) == 0);
            #pragma unroll
            for (int mt = 0; mt < 2; ++mt)
                #pragma unroll
                for (int nt = 0; nt < 4; ++nt) {
                    float* d = acc[mt][nt];
                    float v0 = d[0] + bx[nt], v1 = d[1] + by[nt];
                    float v2 = d[2] + bx[nt], v3 = d[3] + by[nt];
                    v0 = v0 >= 0.f ? v0 : 0.2f * v0;
                    v1 = v1 >= 0.f ? v1 : 0.2f * v1;
                    v2 = v2 >= 0.f ? v2 : 0.2f * v2;
                    v3 = v3 >= 0.f ? v3 : 0.2f * v3;
                    float u0 = fmaxf(v0, __shfl_xor_sync(0xffffffffu, v0, 4));
                    float u1 = fmaxf(v1, __shfl_xor_sync(0xffffffffu, v1, 4));
                    float u2 = fmaxf(v2, __shfl_xor_sync(0xffffffffu, v2, 4));
                    float u3 = fmaxf(v3, __shfl_xor_sync(0xffffffffu, v3, 4));
                    if (storer) {
                        const int o0 = wn + nt * 8 + (l & 3) * 2;
                        const int jl = (wm + mt * 16 + r2) >> 1;   // 0..31
                        *(float2*)&stagef[jl * STAGE_STRIDE + o0] = make_float2(u0, u1);
                        *(float2*)&stagef[(jl + 4) * STAGE_STRIDE + o0] = make_float2(u2, u3);
                    }
                }
            __syncthreads();   // STS (buf^1) + stage complete

            // ---- 5. coalesced store: 32 rows x 128 floats ----
            const int jbase = tile << 5;
            #pragma unroll
            for (int k = 0; k < 4; ++k) {
                int idx = tid + k * THREADS;
                int row = idx >> 5, c4 = idx & 31;
                if (jbase + row < Lout) {
                    float4 v = *(const float4*)&stagef[row * STAGE_STRIDE + c4 * 4];
                    *(float4*)&Yout[(size_t)(jbase + row) * CCH + c4 * 4] = v;
                }
            }
            __syncthreads();   // stage free before next epilogue
            cur ^= 1;
        }

        grid_barrier();        // level complete chip-wide
        Xcur = Yout;
        L = Lout;
    }
}

// ---------------------------------------------------------------------------
extern "C" void kernel_launch(void* const* d_in, const int* in_sizes, int n_in,
                              void* d_out, int out_size) {
    const float* x     = (const float*)d_in[0];
    const float* depth = (const float*)d_in[1];
    const float* W     = (const float*)d_in[2];
    const float* b     = (const float*)d_in[3];
    const int*   perm  = (const int*)d_in[4];
    float* out = (float*)d_out;

    int N = in_sizes[0] / CCH;
    int nlev = 0;
    { int L = N; while (L > 1) { L = (L - 1) / 2; nlev++; } }

    cudaFuncSetAttribute((const void*)persistent_kernel,
                         cudaFuncAttributeMaxDynamicSharedMemorySize, SM_TOT);

    precompute_kernel<<<GRIDP, 256>>>(W, b, depth, nlev);

    float *bufA, *bufB;
    cudaGetSymbolAddress((void**)&bufA, g_bufA);
    cudaGetSymbolAddress((void**)&bufB, g_bufB);

    persistent_kernel<<<GRIDP, THREADS, SM_TOT>>>(x, perm, bufA, bufB, out, N);
}

// round 16
// speedup vs baseline: 2.1627x; 1.0433x over previous
#include <cuda_runtime.h>
#include <cuda_fp16.h>
#include <stdint.h>

#define CCH 128
#define THREADS 256
#define GRIDP 148            // persistent grid: 1 CTA/SM, all co-resident

// ---- device scratch ----
__device__ float    g_bias[32 * CCH];
__device__ uint32_t g_Wtm[CCH][128];        // [o][k/2] fp16x2 of Acat=[W0 W1]
__device__ uint32_t g_PA[262144 * 64];      // fp16 plane: even-level outputs
__device__ uint32_t g_PB[131072 * 64];      // fp16 plane: odd-level outputs
__device__ int      g_barCount;
__device__ volatile unsigned g_barGen;

// ---- SMEM layout (bytes) ----
#define XBUF(buf) ((buf) * 16640)    // X: 65 rows x 256B fp16, double buffered
#define SM_WH   33280                // W: 128 rows x 512B fp16
#define SM_STAGE 98816               // 32 rows x 272B fp16 stage
#define SM_TOT  107520
#define STG_ROW 272

__device__ __forceinline__ uint32_t smem_u32(const void* p) {
    uint32_t a;
    asm("{ .reg .u64 t; cvta.to.shared.u64 t, %1; cvt.u32.u64 %0, t; }" : "=r"(a) : "l"(p));
    return a;
}
__device__ __forceinline__ void ldx4(uint32_t& r0, uint32_t& r1, uint32_t& r2, uint32_t& r3,
                                     uint32_t addr) {
    asm volatile("ldmatrix.sync.aligned.m8n8.x4.shared.b16 {%0,%1,%2,%3}, [%4];"
                 : "=r"(r0), "=r"(r1), "=r"(r2), "=r"(r3) : "r"(addr));
}
__device__ __forceinline__ void mma_f16(float* d, const uint32_t* a, const uint32_t* b) {
    asm volatile("mma.sync.aligned.m16n8k16.row.col.f32.f16.f16.f32 "
                 "{%0,%1,%2,%3}, {%4,%5,%6,%7}, {%8,%9}, {%0,%1,%2,%3};"
                 : "+f"(d[0]), "+f"(d[1]), "+f"(d[2]), "+f"(d[3])
                 : "r"(a[0]), "r"(a[1]), "r"(a[2]), "r"(a[3]), "r"(b[0]), "r"(b[1]));
}
#define STS64(addr, x, y) \
    asm volatile("st.shared.v2.u32 [%0], {%1,%2};" :: "r"(addr), "r"(x), "r"(y) : "memory")
#define STS32(addr, x) \
    asm volatile("st.shared.u32 [%0], %1;" :: "r"(addr), "r"(x) : "memory")
#define CP_ASYNC16(dst, src) \
    asm volatile("cp.async.cg.shared.global [%0], [%1], 16;" :: "r"(dst), "l"(src) : "memory")
#define CP_COMMIT() asm volatile("cp.async.commit_group;" ::: "memory")
#define CP_WAIT1()  asm volatile("cp.async.wait_group 1;" ::: "memory")

// convert float4 -> fp16x4, store to X plane
__device__ __forceinline__ void cvt_sts(float4 v, uint32_t dstH) {
    __half2 hp0 = {__float2half_rn(v.x), __float2half_rn(v.y)};
    __half2 hp1 = {__float2half_rn(v.z), __float2half_rn(v.w)};
    STS64(dstH, *(uint32_t*)&hp0, *(uint32_t*)&hp1);
}
__device__ __forceinline__ uint32_t pack_h2(float a, float b) {
    __half2 h = {__float2half_rn(a), __float2half_rn(b)};
    return *(uint32_t*)&h;
}

// sense-reversing grid barrier; safe: all GRIDP CTAs co-resident.
__device__ __forceinline__ void grid_barrier() {
    __syncthreads();
    if (threadIdx.x == 0) {
        unsigned gen = g_barGen;
        __threadfence();
        if (atomicAdd(&g_barCount, 1) == (int)gridDim.x - 1) {
            g_barCount = 0;
            __threadfence();
            g_barGen = gen + 1;
        } else {
            while (g_barGen == gen) { }
        }
        __threadfence();
    }
    __syncthreads();
}

// ---------------------------------------------------------------------------
__global__ void precompute_kernel(const float* __restrict__ W,
                                  const float* __restrict__ b,
                                  const float* __restrict__ depth,
                                  int nlev) {
    const int tid = threadIdx.x;
    const int gid = blockIdx.x * blockDim.x + tid;
    const int gsize = gridDim.x * blockDim.x;

    for (int i = gid; i < CCH * 128; i += gsize) {
        int o = (i >> 7) & 127, col = i & 127;
        uint32_t out = 0;
        #pragma unroll
        for (int h = 0; h < 2; ++h) {
            int c = 2 * col + h;
            float w = (c < 128) ? W[(size_t)o * 512 + c * 2]
                                : W[(size_t)o * 512 + (c - 128) * 2 + 1];
            __half hv = __float2half_rn(w);
            uint16_t bits = *(uint16_t*)&hv;
            out |= (uint32_t)bits << (16 * h);
        }
        g_Wtm[o][col] = out;
    }

    const int l = tid & 31;
    const int gw = gid >> 5;
    const int nwarps = gsize >> 5;
    for (int p = gw; p < nlev * CCH; p += nwarps) {
        const int lev = p >> 7, o = p & 127;
        float s = 0.f;
        #pragma unroll
        for (int cc = 0; cc < 4; ++cc) {
            int c = l + cc * 32;
            float ws = W[(size_t)o * 512 + (128 + c) * 2 + 0] +
                       W[(size_t)o * 512 + (128 + c) * 2 + 1];
            s += ws * depth[lev * CCH + c];
        }
        #pragma unroll
        for (int d = 16; d > 0; d >>= 1)
            s += __shfl_xor_sync(0xffffffffu, s, d);
        if (l == 0) g_bias[lev * CCH + o] = b[o] + s;
    }
}

// ---------------------------------------------------------------------------
// Persistent kernel. Level 0: fp32 perm gather + register-prefetch pipeline.
// Levels >=1: fp16 plane input via double-buffered cp.async (no regs, no cvt).
// All levels output fp16 planes; final level also writes fp32 out.
// ---------------------------------------------------------------------------
__global__ __launch_bounds__(THREADS)
void persistent_kernel(const float* __restrict__ Xin, const int* __restrict__ perm,
                       float* __restrict__ outp, int N) {
    extern __shared__ char smem[];
    const uint32_t sb = smem_u32(smem);
    char* stage = smem + SM_STAGE;
    const int tid = threadIdx.x, l = tid & 31, wid = tid >> 5;
    const int wm = (wid >> 2) * 32, wn = (wid & 3) * 32;
    const int bid = blockIdx.x;

    // ---- W -> smem once ----
    for (int i = tid; i < 128 * 64; i += THREADS) {
        int o = i >> 6, u = i & 63;
        uint2 v = ((const uint2*)&g_Wtm[o][0])[u];
        uint32_t byte = (uint32_t)o * 512 + (((uint32_t)u * 8) ^ (uint32_t)((o & 7) << 4));
        STS64(sb + SM_WH + byte, v.x, v.y);
    }

    // ---- fragment address constants ----
    const int arl = ((l >> 3) & 1) * 8 + (l & 7);
    uint32_t aAddr[2][2], aS[2][2];
    #pragma unroll
    for (int mt = 0; mt < 2; ++mt)
        #pragma unroll
        for (int tap = 0; tap < 2; ++tap) {
            int row = wm + mt * 16 + arl + tap;
            aAddr[mt][tap] = (uint32_t)row * 256;
            aS[mt][tap] = (uint32_t)((row & 7) << 4);
        }
    uint32_t bRow[2], bS[2];
    #pragma unroll
    for (int g = 0; g < 2; ++g) {
        int o = wn + g * 16 + ((l >> 4) & 1) * 8 + (l & 7);
        bRow[g] = (uint32_t)o * 512;
        bS[g] = (uint32_t)((o & 7) << 4);
    }
    const uint32_t a_k8b = ((l >> 4) & 1) * 16;
    const uint32_t b_k8b = ((l >> 3) & 1) * 16;
    const uint32_t xswz = ((uint32_t)l * 8) ^ ((uint32_t)wid << 4);
    const int r2 = l >> 2;
    const bool storer = ((r2 & 1) == 0);

    int L = N;
    for (int lvl = 0; L > 1; ++lvl) {
        const int Lout = (L - 1) >> 1;
        const bool final = (Lout == 1);
        const int ntiles = (Lout + 31) >> 5;
        uint32_t* dstP = (lvl & 1) ? g_PB : g_PA;
        const uint32_t* srcP = (lvl & 1) ? g_PA : g_PB;   // valid for lvl >= 1

        float bx[4], by[4];
        #pragma unroll
        for (int nt = 0; nt < 4; ++nt) {
            float2 bb = *(const float2*)&g_bias[lvl * CCH + wn + nt * 8 + (l & 3) * 2];
            bx[nt] = bb.x; by[nt] = bb.y;
        }

        int cur = 0;

        if (lvl == 0) {
            // ======== level 0: fp32 gather + register-prefetch pipeline ========
            if (bid < ntiles) {
                const int pbase = bid << 6;
                #pragma unroll
                for (int s9 = 0; s9 < 9; ++s9) {
                    if (s9 == 8 && wid != 0) break;
                    int row = s9 * 8 + wid;
                    int pin = pbase + row; if (pin > L - 1) pin = L - 1;
                    float4 v = *((const float4*)(Xin + (size_t)perm[pin] * CCH) + l);
                    cvt_sts(v, sb + XBUF(0) + (uint32_t)row * 256 + xswz);
                }
            }
            __syncthreads();

            for (int tile = bid; tile < ntiles; tile += GRIDP) {
                const int nexttile = tile + GRIDP;
                const bool hasnext = nexttile < ntiles;

                float4 pr[9];
                if (hasnext) {
                    const int pbase = nexttile << 6;
                    #pragma unroll
                    for (int s9 = 0; s9 < 9; ++s9) {
                        if (s9 == 8 && wid != 0) break;
                        int row = s9 * 8 + wid;
                        int pin = pbase + row; if (pin > L - 1) pin = L - 1;
                        pr[s9] = *((const float4*)(Xin + (size_t)perm[pin] * CCH) + l);
                    }
                }

                float acc[2][4][4];
                #pragma unroll
                for (int mt = 0; mt < 2; ++mt)
                    #pragma unroll
                    for (int nt = 0; nt < 4; ++nt)
                        #pragma unroll
                        for (int r = 0; r < 4; ++r) acc[mt][nt][r] = 0.f;

                const uint32_t xbH = sb + XBUF(cur);
                #pragma unroll
                for (int kt = 0; kt < 16; ++kt) {
                    const int tap = kt >> 3;
                    const uint32_t chA = (uint32_t)(kt & 7) * 32 + a_k8b;
                    const uint32_t chB = (uint32_t)kt * 32 + b_k8b;
                    uint32_t Bh[4][2];
                    ldx4(Bh[0][0], Bh[0][1], Bh[1][0], Bh[1][1], sb + SM_WH + bRow[0] + (chB ^ bS[0]));
                    ldx4(Bh[2][0], Bh[2][1], Bh[3][0], Bh[3][1], sb + SM_WH + bRow[1] + (chB ^ bS[1]));
                    #pragma unroll
                    for (int mt = 0; mt < 2; ++mt) {
                        uint32_t Ah[4];
                        ldx4(Ah[0], Ah[1], Ah[2], Ah[3],
                             xbH + aAddr[mt][tap] + (chA ^ aS[mt][tap]));
                        #pragma unroll
                        for (int nt = 0; nt < 4; ++nt)
                            mma_f16(acc[mt][nt], Ah, Bh[nt]);
                    }
                }

                if (hasnext) {
                    const uint32_t dH = sb + XBUF(cur ^ 1);
                    #pragma unroll
                    for (int s9 = 0; s9 < 9; ++s9) {
                        if (s9 == 8 && wid != 0) break;
                        cvt_sts(pr[s9], dH + (uint32_t)(s9 * 8 + wid) * 256 + xswz);
                    }
                }

                // epilogue: bias + leaky + pool -> fp16 stage -> plane store
                #pragma unroll
                for (int mt = 0; mt < 2; ++mt)
                    #pragma unroll
                    for (int nt = 0; nt < 4; ++nt) {
                        float* d = acc[mt][nt];
                        float v0 = d[0] + bx[nt], v1 = d[1] + by[nt];
                        float v2 = d[2] + bx[nt], v3 = d[3] + by[nt];
                        v0 = v0 >= 0.f ? v0 : 0.2f * v0;
                        v1 = v1 >= 0.f ? v1 : 0.2f * v1;
                        v2 = v2 >= 0.f ? v2 : 0.2f * v2;
                        v3 = v3 >= 0.f ? v3 : 0.2f * v3;
                        float u0 = fmaxf(v0, __shfl_xor_sync(0xffffffffu, v0, 4));
                        float u1 = fmaxf(v1, __shfl_xor_sync(0xffffffffu, v1, 4));
                        float u2 = fmaxf(v2, __shfl_xor_sync(0xffffffffu, v2, 4));
                        float u3 = fmaxf(v3, __shfl_xor_sync(0xffffffffu, v3, 4));
                        if (storer) {
                            const int oc = wn + nt * 8 + (l & 3) * 2;
                            const int jl = (wm + mt * 16 + r2) >> 1;   // 0..31
                            STS32(sb + SM_STAGE + jl * STG_ROW + oc * 2, pack_h2(u0, u1));
                            STS32(sb + SM_STAGE + (jl + 4) * STG_ROW + oc * 2, pack_h2(u2, u3));
                        }
                    }
                __syncthreads();   // STS (buf^1) + stage complete

                const int jbase = tile << 5;
                #pragma unroll
                for (int k = 0; k < 2; ++k) {
                    int idx = tid + k * THREADS;            // 0..511
                    int row = idx >> 4, c = idx & 15;
                    if (jbase + row < Lout) {
                        uint4 v = *(const uint4*)(stage + row * STG_ROW + c * 16);
                        *(uint4*)(dstP + (size_t)(jbase + row) * 64 + c * 4) = v;
                    }
                }
                __syncthreads();
                cur ^= 1;
            }
        } else {
            // ======== levels >= 1: cp.async fp16 planes, double buffered ========
            if (bid < ntiles) {
                const int pbase = bid << 6;
                for (int i = tid; i < 65 * 16; i += THREADS) {
                    int row = i >> 4, c = i & 15;
                    int rin = pbase + row; if (rin > L - 1) rin = L - 1;
                    uint32_t d = XBUF(0) + (uint32_t)row * 256 +
                                 (((uint32_t)c * 16) ^ (uint32_t)((row & 7) << 4));
                    CP_ASYNC16(sb + d, srcP + (size_t)rin * 64 + c * 4);
                }
            }
            CP_COMMIT();

            for (int tile = bid; tile < ntiles; tile += GRIDP) {
                const int nexttile = tile + GRIDP;
                if (nexttile < ntiles) {
                    const int pbase = nexttile << 6;
                    for (int i = tid; i < 65 * 16; i += THREADS) {
                        int row = i >> 4, c = i & 15;
                        int rin = pbase + row; if (rin > L - 1) rin = L - 1;
                        uint32_t d = XBUF(cur ^ 1) + (uint32_t)row * 256 +
                                     (((uint32_t)c * 16) ^ (uint32_t)((row & 7) << 4));
                        CP_ASYNC16(sb + d, srcP + (size_t)rin * 64 + c * 4);
                    }
                }
                CP_COMMIT();
                CP_WAIT1();        // buf[cur] complete (older group)
                __syncthreads();

                float acc[2][4][4];
                #pragma unroll
                for (int mt = 0; mt < 2; ++mt)
                    #pragma unroll
                    for (int nt = 0; nt < 4; ++nt)
                        #pragma unroll
                        for (int r = 0; r < 4; ++r) acc[mt][nt][r] = 0.f;

                const uint32_t xbH = sb + XBUF(cur);
                #pragma unroll
                for (int kt = 0; kt < 16; ++kt) {
                    const int tap = kt >> 3;
                    const uint32_t chA = (uint32_t)(kt & 7) * 32 + a_k8b;
                    const uint32_t chB = (uint32_t)kt * 32 + b_k8b;
                    uint32_t Bh[4][2];
                    ldx4(Bh[0][0], Bh[0][1], Bh[1][0], Bh[1][1], sb + SM_WH + bRow[0] + (chB ^ bS[0]));
                    ldx4(Bh[2][0], Bh[2][1], Bh[3][0], Bh[3][1], sb + SM_WH + bRow[1] + (chB ^ bS[1]));
                    #pragma unroll
                    for (int mt = 0; mt < 2; ++mt) {
                        uint32_t Ah[4];
                        ldx4(Ah[0], Ah[1], Ah[2], Ah[3],
                             xbH + aAddr[mt][tap] + (chA ^ aS[mt][tap]));
                        #pragma unroll
                        for (int nt = 0; nt < 4; ++nt)
                            mma_f16(acc[mt][nt], Ah, Bh[nt]);
                    }
                }

                // epilogue: bias + leaky + pool -> fp16 stage -> plane store
                #pragma unroll
                for (int mt = 0; mt < 2; ++mt)
                    #pragma unroll
                    for (int nt = 0; nt < 4; ++nt) {
                        float* d = acc[mt][nt];
                        float v0 = d[0] + bx[nt], v1 = d[1] + by[nt];
                        float v2 = d[2] + bx[nt], v3 = d[3] + by[nt];
                        v0 = v0 >= 0.f ? v0 : 0.2f * v0;
                        v1 = v1 >= 0.f ? v1 : 0.2f * v1;
                        v2 = v2 >= 0.f ? v2 : 0.2f * v2;
                        v3 = v3 >= 0.f ? v3 : 0.2f * v3;
                        float u0 = fmaxf(v0, __shfl_xor_sync(0xffffffffu, v0, 4));
                        float u1 = fmaxf(v1, __shfl_xor_sync(0xffffffffu, v1, 4));
                        float u2 = fmaxf(v2, __shfl_xor_sync(0xffffffffu, v2, 4));
                        float u3 = fmaxf(v3, __shfl_xor_sync(0xffffffffu, v3, 4));
                        if (storer) {
                            const int oc = wn + nt * 8 + (l & 3) * 2;
                            const int jl = (wm + mt * 16 + r2) >> 1;   // 0..31
                            STS32(sb + SM_STAGE + jl * STG_ROW + oc * 2, pack_h2(u0, u1));
                            STS32(sb + SM_STAGE + (jl + 4) * STG_ROW + oc * 2, pack_h2(u2, u3));
                            if (final && (wm + mt * 16 + r2) == 0) {
                                outp[oc] = u0;
                                outp[oc + 1] = u1;
                            }
                        }
                    }
                __syncthreads();   // stage complete; all MMA reads of buf done

                const int jbase = tile << 5;
                #pragma unroll
                for (int k = 0; k < 2; ++k) {
                    int idx = tid + k * THREADS;
                    int row = idx >> 4, c = idx & 15;
                    if (jbase + row < Lout) {
                        uint4 v = *(const uint4*)(stage + row * STG_ROW + c * 16);
                        *(uint4*)(dstP + (size_t)(jbase + row) * 64 + c * 4) = v;
                    }
                }
                __syncthreads();
                cur ^= 1;
            }
        }

        grid_barrier();
        L = Lout;
    }
}

// ---------------------------------------------------------------------------
extern "C" void kernel_launch(void* const* d_in, const int* in_sizes, int n_in,
                              void* d_out, int out_size) {
    const float* x     = (const float*)d_in[0];
    const float* depth = (const float*)d_in[1];
    const float* W     = (const float*)d_in[2];
    const float* b     = (const float*)d_in[3];
    const int*   perm  = (const int*)d_in[4];
    float* out = (float*)d_out;

    int N = in_sizes[0] / CCH;
    int nlev = 0;
    { int L = N; while (L > 1) { L = (L - 1) / 2; nlev++; } }

    cudaFuncSetAttribute((const void*)persistent_kernel,
                         cudaFuncAttributeMaxDynamicSharedMemorySize, SM_TOT);

    precompute_kernel<<<GRIDP, 256>>>(W, b, depth, nlev);
    persistent_kernel<<<GRIDP, THREADS, SM_TOT>>>(x, perm, out, N);
}